// round 1
// baseline (speedup 1.0000x reference)
#include <cuda_runtime.h>
#include <cuda_bf16.h>

// Problem constants
#define B_ 2
#define S_ 2048
#define D_ 1024
#define H_ 16
#define DK_ 64

static const size_t BSD  = (size_t)B_ * S_ * D_;            // 4,194,304
static const size_t BHSS = (size_t)B_ * H_ * S_ * S_;       // 134,217,728

// Device scratch (allocation-free rule: __device__ globals)
__device__ float g_Qh[B_ * H_ * S_ * DK_];   // [b,h,s,dk]
__device__ float g_Kh[B_ * H_ * S_ * DK_];
__device__ float g_Vh[B_ * H_ * S_ * DK_];
__device__ float g_Ctx[B_ * S_ * D_];        // [b,s,D]
__device__ float g_Attn[(size_t)B_ * H_ * S_ * S_];   // 512 MB scratch (used if attn not an output)
__device__ float g_OutSpare[B_ * S_ * D_];   // used only if out is not an output

// ---------------------------------------------------------------------------
// GEMM: Y = X @ W^T + bias.  X: [M, 1024] row-major, W: [1024, 1024] row-major
// (torch Linear), M = 4096. Tile: BM=128, BN=64, BK=16. 256 threads, 8x4/thread.
// headMajor=1 -> write Y[b,h,s,dk] layout; else plain [M, 1024].
// ---------------------------------------------------------------------------
__global__ __launch_bounds__(256) void gemm_xwT(
    const float* __restrict__ X, const float* __restrict__ W,
    const float* __restrict__ bias, float* __restrict__ Y, int headMajor)
{
    const int bn = blockIdx.x * 64;
    const int bm = blockIdx.y * 128;
    const int t  = threadIdx.x;
    const int tx = t & 15;   // n group (4 cols)
    const int ty = t >> 4;   // m group (8 rows)

    __shared__ float As[16][128];  // As[k][m] (transposed)
    __shared__ float Bs[16][64];   // Bs[k][n]

    float acc[8][4];
    #pragma unroll
    for (int i = 0; i < 8; i++)
        #pragma unroll
        for (int j = 0; j < 4; j++) acc[i][j] = 0.0f;

    const int xr = t >> 2;         // 0..63
    const int xc = (t & 3) * 4;    // 0,4,8,12

    for (int k0 = 0; k0 < D_; k0 += 16) {
        #pragma unroll
        for (int i = 0; i < 2; ++i) {
            int row = i * 64 + xr;
            float4 xv = *(const float4*)(X + (size_t)(bm + row) * D_ + k0 + xc);
            As[xc + 0][row] = xv.x; As[xc + 1][row] = xv.y;
            As[xc + 2][row] = xv.z; As[xc + 3][row] = xv.w;
        }
        {
            float4 wv = *(const float4*)(W + (size_t)(bn + xr) * D_ + k0 + xc);
            Bs[xc + 0][xr] = wv.x; Bs[xc + 1][xr] = wv.y;
            Bs[xc + 2][xr] = wv.z; Bs[xc + 3][xr] = wv.w;
        }
        __syncthreads();
        #pragma unroll
        for (int kk = 0; kk < 16; ++kk) {
            float a[8], b[4];
            #pragma unroll
            for (int i = 0; i < 8; i++) a[i] = As[kk][ty * 8 + i];
            #pragma unroll
            for (int j = 0; j < 4; j++) b[j] = Bs[kk][tx * 4 + j];
            #pragma unroll
            for (int i = 0; i < 8; i++)
                #pragma unroll
                for (int j = 0; j < 4; j++)
                    acc[i][j] = fmaf(a[i], b[j], acc[i][j]);
        }
        __syncthreads();
    }

    #pragma unroll
    for (int i = 0; i < 8; i++) {
        int m  = bm + ty * 8 + i;
        int bb = m >> 11;        // / S_
        int ss = m & (S_ - 1);
        #pragma unroll
        for (int j = 0; j < 4; j++) {
            int n = bn + tx * 4 + j;
            float val = acc[i][j] + bias[n];
            if (headMajor) {
                int h  = n >> 6;
                int d0 = n & 63;
                g_Qh[0]; // no-op to keep symbol refs stable
                ((float*)Y)[(((size_t)bb * H_ + h) * S_ + ss) * DK_ + d0] = val;
            } else {
                Y[(size_t)m * D_ + n] = val;
            }
        }
    }
}

// ---------------------------------------------------------------------------
// Scores: attn_raw[z,q,k] = (1/8) * dot(Qh[z,q,:], Kh[z,k,:]), z = b*H+h.
// 64x64 tiles, K=64 fully in smem. Skips fully-masked tiles (k0 > q0+63).
// ---------------------------------------------------------------------------
__global__ __launch_bounds__(256) void scores_kernel(
    const float* __restrict__ Qh, const float* __restrict__ Kh,
    float* __restrict__ attn)
{
    const int k0 = blockIdx.x * 64;
    const int q0 = blockIdx.y * 64;
    if (k0 > q0 + 63) return;   // fully masked tile; softmax writes the zeros
    const int z = blockIdx.z;

    const float* Q = Qh + (size_t)z * S_ * DK_;
    const float* K = Kh + (size_t)z * S_ * DK_;
    float* A = attn + (size_t)z * S_ * S_;

    __shared__ float Qs[64][64];   // Qs[k][q] transposed
    __shared__ float Ks[64][64];   // Ks[k][n] transposed

    const int t  = threadIdx.x;
    const int tx = t & 15;
    const int ty = t >> 4;

    #pragma unroll
    for (int i = 0; i < 4; i++) {
        int row = i * 16 + (t >> 4);
        int c4  = (t & 15) * 4;
        float4 qv = *(const float4*)(Q + (size_t)(q0 + row) * DK_ + c4);
        Qs[c4 + 0][row] = qv.x; Qs[c4 + 1][row] = qv.y;
        Qs[c4 + 2][row] = qv.z; Qs[c4 + 3][row] = qv.w;
        float4 kv = *(const float4*)(K + (size_t)(k0 + row) * DK_ + c4);
        Ks[c4 + 0][row] = kv.x; Ks[c4 + 1][row] = kv.y;
        Ks[c4 + 2][row] = kv.z; Ks[c4 + 3][row] = kv.w;
    }
    __syncthreads();

    float acc[4][4];
    #pragma unroll
    for (int i = 0; i < 4; i++)
        #pragma unroll
        for (int j = 0; j < 4; j++) acc[i][j] = 0.0f;

    #pragma unroll 8
    for (int kk = 0; kk < 64; ++kk) {
        float a[4], b[4];
        #pragma unroll
        for (int i = 0; i < 4; i++) a[i] = Qs[kk][ty * 4 + i];
        #pragma unroll
        for (int j = 0; j < 4; j++) b[j] = Ks[kk][tx * 4 + j];
        #pragma unroll
        for (int i = 0; i < 4; i++)
            #pragma unroll
            for (int j = 0; j < 4; j++)
                acc[i][j] = fmaf(a[i], b[j], acc[i][j]);
    }

    const float sc = 0.125f;  // 1/sqrt(64)
    #pragma unroll
    for (int i = 0; i < 4; i++) {
        int q = q0 + ty * 4 + i;
        #pragma unroll
        for (int j = 0; j < 4; j++) {
            int k = k0 + tx * 4 + j;
            A[(size_t)q * S_ + k] = acc[i][j] * sc;  // k>q garbage; zeroed by softmax
        }
    }
}

// ---------------------------------------------------------------------------
// Causal row softmax, in place. One block per row; zeroes masked tail (k>q).
// ---------------------------------------------------------------------------
__global__ __launch_bounds__(256) void softmax_kernel(float* __restrict__ attn)
{
    const int q = blockIdx.x;
    const int z = blockIdx.y;
    float* row = attn + ((size_t)z * S_ + q) * S_;
    const int L = q + 1;
    const int t = threadIdx.x;
    __shared__ float red[256];

    float m = -1e30f;
    for (int k = t; k < L; k += 256) m = fmaxf(m, row[k]);
    red[t] = m; __syncthreads();
    for (int s = 128; s > 0; s >>= 1) {
        if (t < s) red[t] = fmaxf(red[t], red[t + s]);
        __syncthreads();
    }
    m = red[0]; __syncthreads();

    float sum = 0.0f;
    for (int k = t; k < L; k += 256) {
        float e = __expf(row[k] - m);
        row[k] = e;
        sum += e;
    }
    red[t] = sum; __syncthreads();
    for (int s = 128; s > 0; s >>= 1) {
        if (t < s) red[t] += red[t + s];
        __syncthreads();
    }
    const float inv = 1.0f / red[0];
    __syncthreads();

    for (int k = t; k < L; k += 256) row[k] *= inv;
    for (int k = L + t; k < S_; k += 256) row[k] = 0.0f;
}

// ---------------------------------------------------------------------------
// PV: ctx[b, q, h*64+d] = sum_k attn[z,q,k] * Vh[z,k,d]. Causal k-range only.
// ---------------------------------------------------------------------------
__global__ __launch_bounds__(256) void pv_kernel(
    const float* __restrict__ attn, const float* __restrict__ Vh,
    float* __restrict__ ctx)
{
    const int q0 = blockIdx.x * 64;
    const int z  = blockIdx.y;
    const int bb = z >> 4;     // / H_
    const int hh = z & 15;

    const float* A = attn + (size_t)z * S_ * S_;
    const float* V = Vh + (size_t)z * S_ * DK_;

    __shared__ float As[16][64];   // As[k][q]
    __shared__ float Vs[16][64];   // Vs[k][d]

    const int t  = threadIdx.x;
    const int tx = t & 15;
    const int ty = t >> 4;

    float acc[4][4];
    #pragma unroll
    for (int i = 0; i < 4; i++)
        #pragma unroll
        for (int j = 0; j < 4; j++) acc[i][j] = 0.0f;

    const int lr = t >> 2;
    const int lc = (t & 3) * 4;
    const int kmax = q0 + 64;   // beyond this attn is exactly 0

    for (int kt = 0; kt < kmax; kt += 16) {
        float4 av = *(const float4*)(A + (size_t)(q0 + lr) * S_ + kt + lc);
        As[lc + 0][lr] = av.x; As[lc + 1][lr] = av.y;
        As[lc + 2][lr] = av.z; As[lc + 3][lr] = av.w;

        float4 vv = *(const float4*)(V + (size_t)(kt + (t >> 4)) * DK_ + (t & 15) * 4);
        ((float4*)&Vs[t >> 4][0])[t & 15] = vv;
        __syncthreads();

        #pragma unroll
        for (int kk = 0; kk < 16; ++kk) {
            float a[4], b[4];
            #pragma unroll
            for (int i = 0; i < 4; i++) a[i] = As[kk][ty * 4 + i];
            #pragma unroll
            for (int j = 0; j < 4; j++) b[j] = Vs[kk][tx * 4 + j];
            #pragma unroll
            for (int i = 0; i < 4; i++)
                #pragma unroll
                for (int j = 0; j < 4; j++)
                    acc[i][j] = fmaf(a[i], b[j], acc[i][j]);
        }
        __syncthreads();
    }

    #pragma unroll
    for (int i = 0; i < 4; i++) {
        int q = q0 + ty * 4 + i;
        #pragma unroll
        for (int j = 0; j < 4; j++) {
            int d = tx * 4 + j;
            ctx[((size_t)bb * S_ + q) * D_ + hh * DK_ + d] = acc[i][j];
        }
    }
}

// ---------------------------------------------------------------------------
extern "C" void kernel_launch(void* const* d_in, const int* in_sizes, int n_in,
                              void* d_out, int out_size)
{
    const float* q  = (const float*)d_in[0];
    const float* k  = (const float*)d_in[1];
    const float* v  = (const float*)d_in[2];
    // d_in[3] = mask (causal, known), d_in[4] = num_heads (known)
    const float* Wq = (const float*)d_in[5];
    const float* bq = (const float*)d_in[6];
    const float* Wk = (const float*)d_in[7];
    const float* bk = (const float*)d_in[8];
    const float* Wv = (const float*)d_in[9];
    const float* bv = (const float*)d_in[10];
    const float* Wo = (const float*)d_in[11];
    const float* bo = (const float*)d_in[12];

    float *gQh, *gKh, *gVh, *gCtx, *gAttn, *gOutSpare;
    cudaGetSymbolAddress((void**)&gQh,  g_Qh);
    cudaGetSymbolAddress((void**)&gKh,  g_Kh);
    cudaGetSymbolAddress((void**)&gVh,  g_Vh);
    cudaGetSymbolAddress((void**)&gCtx, g_Ctx);
    cudaGetSymbolAddress((void**)&gAttn, g_Attn);
    cudaGetSymbolAddress((void**)&gOutSpare, g_OutSpare);

    // Route outputs by out_size (tuple = (out, attn) flattened in order).
    float* outp = (float*)d_out;
    float* attn = gAttn;
    if ((size_t)out_size == BSD + BHSS) {
        outp = (float*)d_out;
        attn = (float*)d_out + BSD;
    } else if ((size_t)out_size == BHSS) {
        attn = (float*)d_out;
        outp = gOutSpare;
    }

    const dim3 blk(256);
    const dim3 gProj(D_ / 64, (B_ * S_) / 128);        // (16, 32)

    gemm_xwT<<<gProj, blk>>>(q, Wq, bq, gQh, 1);
    gemm_xwT<<<gProj, blk>>>(k, Wk, bk, gKh, 1);
    gemm_xwT<<<gProj, blk>>>(v, Wv, bv, gVh, 1);

    scores_kernel<<<dim3(S_ / 64, S_ / 64, B_ * H_), blk>>>(gQh, gKh, attn);
    softmax_kernel<<<dim3(S_, B_ * H_), blk>>>(attn);
    pv_kernel<<<dim3(S_ / 64, B_ * H_), blk>>>(attn, gVh, gCtx);

    gemm_xwT<<<gProj, blk>>>(gCtx, Wo, bo, outp, 0);
}

// round 2
// speedup vs baseline: 1.0014x; 1.0014x over previous
#include <cuda_runtime.h>
#include <cuda_bf16.h>

// Problem constants
#define B_ 2
#define S_ 2048
#define D_ 1024
#define H_ 16
#define DK_ 64

static const size_t BSD  = (size_t)B_ * S_ * D_;            // 4,194,304
static const size_t BHSS = (size_t)B_ * H_ * S_ * S_;       // 134,217,728

// Device scratch (allocation-free rule: __device__ globals)
__device__ float g_Qh[B_ * H_ * S_ * DK_];   // [b,h,s,dk]
__device__ float g_Kh[B_ * H_ * S_ * DK_];
__device__ float g_Vh[B_ * H_ * S_ * DK_];
__device__ float g_Ctx[B_ * S_ * D_];        // [b,s,D]
__device__ float g_Attn[(size_t)B_ * H_ * S_ * S_];   // 512 MB scratch (used if attn not an output)
__device__ float g_OutSpare[B_ * S_ * D_];   // used only if out is not an output

// ---------------------------------------------------------------------------
// GEMM: Y = X @ W^T + bias.  X: [M, 1024] row-major, W: [1024, 1024] row-major
// (torch Linear), M = 4096. Tile: BM=128, BN=64, BK=16. 256 threads, 8x4/thread.
// headMajor=1 -> write Y[b,h,s,dk] layout; else plain [M, 1024].
// ---------------------------------------------------------------------------
__global__ __launch_bounds__(256) void gemm_xwT(
    const float* __restrict__ X, const float* __restrict__ W,
    const float* __restrict__ bias, float* __restrict__ Y, int headMajor)
{
    const int bn = blockIdx.x * 64;
    const int bm = blockIdx.y * 128;
    const int t  = threadIdx.x;
    const int tx = t & 15;   // n group (4 cols)
    const int ty = t >> 4;   // m group (8 rows)

    __shared__ float As[16][128];  // As[k][m] (transposed)
    __shared__ float Bs[16][64];   // Bs[k][n]

    float acc[8][4];
    #pragma unroll
    for (int i = 0; i < 8; i++)
        #pragma unroll
        for (int j = 0; j < 4; j++) acc[i][j] = 0.0f;

    const int xr = t >> 2;         // 0..63
    const int xc = (t & 3) * 4;    // 0,4,8,12

    for (int k0 = 0; k0 < D_; k0 += 16) {
        #pragma unroll
        for (int i = 0; i < 2; ++i) {
            int row = i * 64 + xr;
            float4 xv = *(const float4*)(X + (size_t)(bm + row) * D_ + k0 + xc);
            As[xc + 0][row] = xv.x; As[xc + 1][row] = xv.y;
            As[xc + 2][row] = xv.z; As[xc + 3][row] = xv.w;
        }
        {
            float4 wv = *(const float4*)(W + (size_t)(bn + xr) * D_ + k0 + xc);
            Bs[xc + 0][xr] = wv.x; Bs[xc + 1][xr] = wv.y;
            Bs[xc + 2][xr] = wv.z; Bs[xc + 3][xr] = wv.w;
        }
        __syncthreads();
        #pragma unroll
        for (int kk = 0; kk < 16; ++kk) {
            float a[8], b[4];
            #pragma unroll
            for (int i = 0; i < 8; i++) a[i] = As[kk][ty * 8 + i];
            #pragma unroll
            for (int j = 0; j < 4; j++) b[j] = Bs[kk][tx * 4 + j];
            #pragma unroll
            for (int i = 0; i < 8; i++)
                #pragma unroll
                for (int j = 0; j < 4; j++)
                    acc[i][j] = fmaf(a[i], b[j], acc[i][j]);
        }
        __syncthreads();
    }

    #pragma unroll
    for (int i = 0; i < 8; i++) {
        int m  = bm + ty * 8 + i;
        int bb = m >> 11;        // / S_
        int ss = m & (S_ - 1);
        #pragma unroll
        for (int j = 0; j < 4; j++) {
            int n = bn + tx * 4 + j;
            float val = acc[i][j] + bias[n];
            if (headMajor) {
                int h  = n >> 6;
                int d0 = n & 63;
                g_Qh[0]; // no-op to keep symbol refs stable
                ((float*)Y)[(((size_t)bb * H_ + h) * S_ + ss) * DK_ + d0] = val;
            } else {
                Y[(size_t)m * D_ + n] = val;
            }
        }
    }
}

// ---------------------------------------------------------------------------
// Scores: attn_raw[z,q,k] = (1/8) * dot(Qh[z,q,:], Kh[z,k,:]), z = b*H+h.
// 64x64 tiles, K=64 fully in smem. Skips fully-masked tiles (k0 > q0+63).
// ---------------------------------------------------------------------------
__global__ __launch_bounds__(256) void scores_kernel(
    const float* __restrict__ Qh, const float* __restrict__ Kh,
    float* __restrict__ attn)
{
    const int k0 = blockIdx.x * 64;
    const int q0 = blockIdx.y * 64;
    if (k0 > q0 + 63) return;   // fully masked tile; softmax writes the zeros
    const int z = blockIdx.z;

    const float* Q = Qh + (size_t)z * S_ * DK_;
    const float* K = Kh + (size_t)z * S_ * DK_;
    float* A = attn + (size_t)z * S_ * S_;

    __shared__ float Qs[64][64];   // Qs[k][q] transposed
    __shared__ float Ks[64][64];   // Ks[k][n] transposed

    const int t  = threadIdx.x;
    const int tx = t & 15;
    const int ty = t >> 4;

    #pragma unroll
    for (int i = 0; i < 4; i++) {
        int row = i * 16 + (t >> 4);
        int c4  = (t & 15) * 4;
        float4 qv = *(const float4*)(Q + (size_t)(q0 + row) * DK_ + c4);
        Qs[c4 + 0][row] = qv.x; Qs[c4 + 1][row] = qv.y;
        Qs[c4 + 2][row] = qv.z; Qs[c4 + 3][row] = qv.w;
        float4 kv = *(const float4*)(K + (size_t)(k0 + row) * DK_ + c4);
        Ks[c4 + 0][row] = kv.x; Ks[c4 + 1][row] = kv.y;
        Ks[c4 + 2][row] = kv.z; Ks[c4 + 3][row] = kv.w;
    }
    __syncthreads();

    float acc[4][4];
    #pragma unroll
    for (int i = 0; i < 4; i++)
        #pragma unroll
        for (int j = 0; j < 4; j++) acc[i][j] = 0.0f;

    #pragma unroll 8
    for (int kk = 0; kk < 64; ++kk) {
        float a[4], b[4];
        #pragma unroll
        for (int i = 0; i < 4; i++) a[i] = Qs[kk][ty * 4 + i];
        #pragma unroll
        for (int j = 0; j < 4; j++) b[j] = Ks[kk][tx * 4 + j];
        #pragma unroll
        for (int i = 0; i < 4; i++)
            #pragma unroll
            for (int j = 0; j < 4; j++)
                acc[i][j] = fmaf(a[i], b[j], acc[i][j]);
    }

    const float sc = 0.125f;  // 1/sqrt(64)
    #pragma unroll
    for (int i = 0; i < 4; i++) {
        int q = q0 + ty * 4 + i;
        #pragma unroll
        for (int j = 0; j < 4; j++) {
            int k = k0 + tx * 4 + j;
            A[(size_t)q * S_ + k] = acc[i][j] * sc;  // k>q garbage; zeroed by softmax
        }
    }
}

// ---------------------------------------------------------------------------
// Causal row softmax, in place. One block per row; zeroes masked tail (k>q).
// ---------------------------------------------------------------------------
__global__ __launch_bounds__(256) void softmax_kernel(float* __restrict__ attn)
{
    const int q = blockIdx.x;
    const int z = blockIdx.y;
    float* row = attn + ((size_t)z * S_ + q) * S_;
    const int L = q + 1;
    const int t = threadIdx.x;
    __shared__ float red[256];

    float m = -1e30f;
    for (int k = t; k < L; k += 256) m = fmaxf(m, row[k]);
    red[t] = m; __syncthreads();
    for (int s = 128; s > 0; s >>= 1) {
        if (t < s) red[t] = fmaxf(red[t], red[t + s]);
        __syncthreads();
    }
    m = red[0]; __syncthreads();

    float sum = 0.0f;
    for (int k = t; k < L; k += 256) {
        float e = __expf(row[k] - m);
        row[k] = e;
        sum += e;
    }
    red[t] = sum; __syncthreads();
    for (int s = 128; s > 0; s >>= 1) {
        if (t < s) red[t] += red[t + s];
        __syncthreads();
    }
    const float inv = 1.0f / red[0];
    __syncthreads();

    for (int k = t; k < L; k += 256) row[k] *= inv;
    for (int k = L + t; k < S_; k += 256) row[k] = 0.0f;
}

// ---------------------------------------------------------------------------
// PV: ctx[b, q, h*64+d] = sum_k attn[z,q,k] * Vh[z,k,d]. Causal k-range only.
// ---------------------------------------------------------------------------
__global__ __launch_bounds__(256) void pv_kernel(
    const float* __restrict__ attn, const float* __restrict__ Vh,
    float* __restrict__ ctx)
{
    const int q0 = blockIdx.x * 64;
    const int z  = blockIdx.y;
    const int bb = z >> 4;     // / H_
    const int hh = z & 15;

    const float* A = attn + (size_t)z * S_ * S_;
    const float* V = Vh + (size_t)z * S_ * DK_;

    __shared__ float As[16][64];   // As[k][q]
    __shared__ float Vs[16][64];   // Vs[k][d]

    const int t  = threadIdx.x;
    const int tx = t & 15;
    const int ty = t >> 4;

    float acc[4][4];
    #pragma unroll
    for (int i = 0; i < 4; i++)
        #pragma unroll
        for (int j = 0; j < 4; j++) acc[i][j] = 0.0f;

    const int lr = t >> 2;
    const int lc = (t & 3) * 4;
    const int kmax = q0 + 64;   // beyond this attn is exactly 0

    for (int kt = 0; kt < kmax; kt += 16) {
        float4 av = *(const float4*)(A + (size_t)(q0 + lr) * S_ + kt + lc);
        As[lc + 0][lr] = av.x; As[lc + 1][lr] = av.y;
        As[lc + 2][lr] = av.z; As[lc + 3][lr] = av.w;

        float4 vv = *(const float4*)(V + (size_t)(kt + (t >> 4)) * DK_ + (t & 15) * 4);
        ((float4*)&Vs[t >> 4][0])[t & 15] = vv;
        __syncthreads();

        #pragma unroll
        for (int kk = 0; kk < 16; ++kk) {
            float a[4], b[4];
            #pragma unroll
            for (int i = 0; i < 4; i++) a[i] = As[kk][ty * 4 + i];
            #pragma unroll
            for (int j = 0; j < 4; j++) b[j] = Vs[kk][tx * 4 + j];
            #pragma unroll
            for (int i = 0; i < 4; i++)
                #pragma unroll
                for (int j = 0; j < 4; j++)
                    acc[i][j] = fmaf(a[i], b[j], acc[i][j]);
        }
        __syncthreads();
    }

    #pragma unroll
    for (int i = 0; i < 4; i++) {
        int q = q0 + ty * 4 + i;
        #pragma unroll
        for (int j = 0; j < 4; j++) {
            int d = tx * 4 + j;
            ctx[((size_t)bb * S_ + q) * D_ + hh * DK_ + d] = acc[i][j];
        }
    }
}

// ---------------------------------------------------------------------------
extern "C" void kernel_launch(void* const* d_in, const int* in_sizes, int n_in,
                              void* d_out, int out_size)
{
    const float* q  = (const float*)d_in[0];
    const float* k  = (const float*)d_in[1];
    const float* v  = (const float*)d_in[2];
    // d_in[3] = mask (causal, known), d_in[4] = num_heads (known)
    const float* Wq = (const float*)d_in[5];
    const float* bq = (const float*)d_in[6];
    const float* Wk = (const float*)d_in[7];
    const float* bk = (const float*)d_in[8];
    const float* Wv = (const float*)d_in[9];
    const float* bv = (const float*)d_in[10];
    const float* Wo = (const float*)d_in[11];
    const float* bo = (const float*)d_in[12];

    float *gQh, *gKh, *gVh, *gCtx, *gAttn, *gOutSpare;
    cudaGetSymbolAddress((void**)&gQh,  g_Qh);
    cudaGetSymbolAddress((void**)&gKh,  g_Kh);
    cudaGetSymbolAddress((void**)&gVh,  g_Vh);
    cudaGetSymbolAddress((void**)&gCtx, g_Ctx);
    cudaGetSymbolAddress((void**)&gAttn, g_Attn);
    cudaGetSymbolAddress((void**)&gOutSpare, g_OutSpare);

    // Route outputs by out_size (tuple = (out, attn) flattened in order).
    float* outp = (float*)d_out;
    float* attn = gAttn;
    if ((size_t)out_size == BSD + BHSS) {
        outp = (float*)d_out;
        attn = (float*)d_out + BSD;
    } else if ((size_t)out_size == BHSS) {
        attn = (float*)d_out;
        outp = gOutSpare;
    }

    const dim3 blk(256);
    const dim3 gProj(D_ / 64, (B_ * S_) / 128);        // (16, 32)

    gemm_xwT<<<gProj, blk>>>(q, Wq, bq, gQh, 1);
    gemm_xwT<<<gProj, blk>>>(k, Wk, bk, gKh, 1);
    gemm_xwT<<<gProj, blk>>>(v, Wv, bv, gVh, 1);

    scores_kernel<<<dim3(S_ / 64, S_ / 64, B_ * H_), blk>>>(gQh, gKh, attn);
    softmax_kernel<<<dim3(S_, B_ * H_), blk>>>(attn);
    pv_kernel<<<dim3(S_ / 64, B_ * H_), blk>>>(attn, gVh, gCtx);

    gemm_xwT<<<gProj, blk>>>(gCtx, Wo, bo, outp, 0);
}

// round 4
// speedup vs baseline: 1.6896x; 1.6872x over previous
#include <cuda_runtime.h>
#include <cstdint>

#define B_ 2
#define S_ 2048
#define D_ 1024
#define H_ 16
#define DK_ 64

static const size_t BSD  = (size_t)B_ * S_ * D_;            // 4,194,304
static const size_t BHSS = (size_t)B_ * H_ * S_ * S_;       // 134,217,728

// Device scratch (allocation-free rule)
__device__ float g_Qh[B_ * H_ * S_ * DK_];          // [z, s, dk]
__device__ float g_Kh[B_ * H_ * S_ * DK_];          // [z, s, dk]
__device__ float g_Vh[B_ * H_ * S_ * DK_];          // [z, s, dk]
__device__ float g_Ctx[B_ * S_ * D_];               // [b, s, D]
__device__ float g_Attn[(size_t)B_ * H_ * S_ * S_]; // scratch if attn not an output
__device__ float g_OutSpare[B_ * S_ * D_];

// ------------------------- helpers -------------------------
__device__ __forceinline__ float tf32r(float x) {   // round-to-nearest tf32
    uint32_t u;
    asm("cvt.rna.tf32.f32 %0, %1;" : "=r"(u) : "f"(x));
    return __uint_as_float(u);
}

__device__ __forceinline__ void mma8(float* c,
    uint32_t a0, uint32_t a1, uint32_t a2, uint32_t a3,
    uint32_t b0, uint32_t b1)
{
    asm volatile(
        "mma.sync.aligned.m16n8k8.row.col.f32.tf32.tf32.f32 "
        "{%0,%1,%2,%3}, {%4,%5,%6,%7}, {%8,%9}, {%0,%1,%2,%3};"
        : "+f"(c[0]), "+f"(c[1]), "+f"(c[2]), "+f"(c[3])
        : "r"(a0), "r"(a1), "r"(a2), "r"(a3), "r"(b0), "r"(b1));
}

__device__ __forceinline__ uint32_t fu(float x) { return __float_as_uint(x); }

// ============================================================================
// Projection (tf32x2 split): Y = X @ W^T + bias.
// X:[4096,1024], W:[1024,1024] row-major. BM=128, BN=128, BK=16.
// 8 warps = 4(m) x 2(n); warp tile 32x64 (mt=2, nt=8).
// mode 0: Y[m,1024]; mode 1: head-major Y[z,s,64].
// ============================================================================
#define PSTR 20   // 16 + 4 pad; (20*m + k) % 32 conflict-free for fragment loads
__global__ __launch_bounds__(256) void proj_mma(
    const float* __restrict__ X, const float* __restrict__ W,
    const float* __restrict__ bias, float* __restrict__ Y, int mode)
{
    __shared__ float sXh[128 * PSTR], sXl[128 * PSTR];
    __shared__ float sWh[128 * PSTR], sWl[128 * PSTR];

    const int t = threadIdx.x;
    const int wid = t >> 5, lane = t & 31, g = lane >> 2, tig = lane & 3;
    const int wm = wid & 3, wn = wid >> 2;
    const int bn = blockIdx.x * 128, bm = blockIdx.y * 128;

    float acc[2][8][4];
    #pragma unroll
    for (int mt = 0; mt < 2; mt++)
        #pragma unroll
        for (int nt = 0; nt < 8; nt++)
            #pragma unroll
            for (int i = 0; i < 4; i++) acc[mt][nt][i] = 0.0f;

    for (int k0 = 0; k0 < D_; k0 += 16) {
        __syncthreads();
        #pragma unroll
        for (int i = 0; i < 2; ++i) {
            int idx = i * 256 + t;
            int row = idx >> 2, c4 = (idx & 3) << 2;
            int so = row * PSTR + c4;
            float4 xv = *(const float4*)(X + (size_t)(bm + row) * D_ + k0 + c4);
            float h0 = tf32r(xv.x), h1 = tf32r(xv.y), h2 = tf32r(xv.z), h3 = tf32r(xv.w);
            *(float4*)(sXh + so) = make_float4(h0, h1, h2, h3);
            *(float4*)(sXl + so) = make_float4(tf32r(xv.x - h0), tf32r(xv.y - h1),
                                               tf32r(xv.z - h2), tf32r(xv.w - h3));
            float4 wv = *(const float4*)(W + (size_t)(bn + row) * D_ + k0 + c4);
            float j0 = tf32r(wv.x), j1 = tf32r(wv.y), j2 = tf32r(wv.z), j3 = tf32r(wv.w);
            *(float4*)(sWh + so) = make_float4(j0, j1, j2, j3);
            *(float4*)(sWl + so) = make_float4(tf32r(wv.x - j0), tf32r(wv.y - j1),
                                               tf32r(wv.z - j2), tf32r(wv.w - j3));
        }
        __syncthreads();

        #pragma unroll
        for (int kk = 0; kk < 16; kk += 8) {
            uint32_t ah[2][4], al[2][4];
            #pragma unroll
            for (int mt = 0; mt < 2; mt++) {
                int m = wm * 32 + mt * 16;
                ah[mt][0] = fu(sXh[(m + g)     * PSTR + kk + tig]);
                ah[mt][1] = fu(sXh[(m + g + 8) * PSTR + kk + tig]);
                ah[mt][2] = fu(sXh[(m + g)     * PSTR + kk + tig + 4]);
                ah[mt][3] = fu(sXh[(m + g + 8) * PSTR + kk + tig + 4]);
                al[mt][0] = fu(sXl[(m + g)     * PSTR + kk + tig]);
                al[mt][1] = fu(sXl[(m + g + 8) * PSTR + kk + tig]);
                al[mt][2] = fu(sXl[(m + g)     * PSTR + kk + tig + 4]);
                al[mt][3] = fu(sXl[(m + g + 8) * PSTR + kk + tig + 4]);
            }
            uint32_t bh[8][2], bl[8][2];
            #pragma unroll
            for (int nt = 0; nt < 8; nt++) {
                int n = wn * 64 + nt * 8;
                bh[nt][0] = fu(sWh[(n + g) * PSTR + kk + tig]);
                bh[nt][1] = fu(sWh[(n + g) * PSTR + kk + tig + 4]);
                bl[nt][0] = fu(sWl[(n + g) * PSTR + kk + tig]);
                bl[nt][1] = fu(sWl[(n + g) * PSTR + kk + tig + 4]);
            }
            #pragma unroll
            for (int mt = 0; mt < 2; mt++)
                #pragma unroll
                for (int nt = 0; nt < 8; nt++) {
                    mma8(acc[mt][nt], ah[mt][0], ah[mt][1], ah[mt][2], ah[mt][3],
                         bh[nt][0], bh[nt][1]);
                    mma8(acc[mt][nt], ah[mt][0], ah[mt][1], ah[mt][2], ah[mt][3],
                         bl[nt][0], bl[nt][1]);
                    mma8(acc[mt][nt], al[mt][0], al[mt][1], al[mt][2], al[mt][3],
                         bh[nt][0], bh[nt][1]);
                }
        }
    }

    // epilogue
    #pragma unroll
    for (int mt = 0; mt < 2; mt++) {
        int r0 = bm + wm * 32 + mt * 16 + g;
        int r1 = r0 + 8;
        #pragma unroll
        for (int nt = 0; nt < 8; nt++) {
            int col = bn + wn * 64 + nt * 8 + 2 * tig;
            float b0v = __ldg(bias + col), b1v = __ldg(bias + col + 1);
            float* c = acc[mt][nt];
            float2 v0 = make_float2(c[0] + b0v, c[1] + b1v);
            float2 v1 = make_float2(c[2] + b0v, c[3] + b1v);
            if (mode == 0) {
                *(float2*)(Y + (size_t)r0 * D_ + col) = v0;
                *(float2*)(Y + (size_t)r1 * D_ + col) = v1;
            } else {
                int h = col >> 6, d0 = col & 63;
                int bb0 = r0 >> 11, ss0 = r0 & (S_ - 1);
                int bb1 = r1 >> 11, ss1 = r1 & (S_ - 1);
                *(float2*)(Y + (((size_t)bb0 * H_ + h) * S_ + ss0) * DK_ + d0) = v0;
                *(float2*)(Y + (((size_t)bb1 * H_ + h) * S_ + ss1) * DK_ + d0) = v1;
            }
        }
    }
}

// ============================================================================
// Scores (plain tf32): attn[z,q,k] = 0.125 * dot(Qh[z,q,:], Kh[z,k,:]).
// Block tile 128(q) x 128(k), dk=64 in 2 chunks of 32.
// 8 warps = 2(m) x 4(n); warp tile 64x32 (mt=4, nt=4). Causal skip k0>q0.
// ============================================================================
#define SSTR 36
__global__ __launch_bounds__(256) void scores_mma(
    const float* __restrict__ Qh, const float* __restrict__ Kh,
    float* __restrict__ attn)
{
    const int k0 = blockIdx.x * 128, q0 = blockIdx.y * 128;
    if (k0 > q0) return;
    const int z = blockIdx.z;

    __shared__ float sQ[128 * SSTR], sK[128 * SSTR];

    const int t = threadIdx.x;
    const int wid = t >> 5, lane = t & 31, g = lane >> 2, tig = lane & 3;
    const int wm = wid & 1, wn = wid >> 1;

    const float* Q = Qh + (size_t)z * S_ * DK_;
    const float* K = Kh + (size_t)z * S_ * DK_;

    float acc[4][4][4];
    #pragma unroll
    for (int mt = 0; mt < 4; mt++)
        #pragma unroll
        for (int nt = 0; nt < 4; nt++)
            #pragma unroll
            for (int i = 0; i < 4; i++) acc[mt][nt][i] = 0.0f;

    #pragma unroll
    for (int kc = 0; kc < 2; kc++) {
        const int c0 = kc * 32;
        __syncthreads();
        #pragma unroll
        for (int i = 0; i < 4; ++i) {
            int idx = i * 256 + t;
            int row = idx >> 3, c4 = (idx & 7) << 2;
            int so = row * SSTR + c4;
            float4 qv = *(const float4*)(Q + (size_t)(q0 + row) * DK_ + c0 + c4);
            *(float4*)(sQ + so) = make_float4(tf32r(qv.x), tf32r(qv.y), tf32r(qv.z), tf32r(qv.w));
            float4 kv = *(const float4*)(K + (size_t)(k0 + row) * DK_ + c0 + c4);
            *(float4*)(sK + so) = make_float4(tf32r(kv.x), tf32r(kv.y), tf32r(kv.z), tf32r(kv.w));
        }
        __syncthreads();

        #pragma unroll
        for (int kk = 0; kk < 32; kk += 8) {
            uint32_t a[4][4];
            #pragma unroll
            for (int mt = 0; mt < 4; mt++) {
                int m = wm * 64 + mt * 16;
                a[mt][0] = fu(sQ[(m + g)     * SSTR + kk + tig]);
                a[mt][1] = fu(sQ[(m + g + 8) * SSTR + kk + tig]);
                a[mt][2] = fu(sQ[(m + g)     * SSTR + kk + tig + 4]);
                a[mt][3] = fu(sQ[(m + g + 8) * SSTR + kk + tig + 4]);
            }
            uint32_t b[4][2];
            #pragma unroll
            for (int nt = 0; nt < 4; nt++) {
                int n = wn * 32 + nt * 8;
                b[nt][0] = fu(sK[(n + g) * SSTR + kk + tig]);
                b[nt][1] = fu(sK[(n + g) * SSTR + kk + tig + 4]);
            }
            #pragma unroll
            for (int mt = 0; mt < 4; mt++)
                #pragma unroll
                for (int nt = 0; nt < 4; nt++)
                    mma8(acc[mt][nt], a[mt][0], a[mt][1], a[mt][2], a[mt][3],
                         b[nt][0], b[nt][1]);
        }
    }

    const float sc = 0.125f;
    #pragma unroll
    for (int mt = 0; mt < 4; mt++) {
        int q = q0 + wm * 64 + mt * 16 + g;
        float* A0 = attn + ((size_t)z * S_ + q) * S_;
        float* A1 = A0 + 8 * S_;
        #pragma unroll
        for (int nt = 0; nt < 4; nt++) {
            int col = k0 + wn * 32 + nt * 8 + 2 * tig;
            float* c = acc[mt][nt];
            *(float2*)(A0 + col) = make_float2(c[0] * sc, c[1] * sc);
            *(float2*)(A1 + col) = make_float2(c[2] * sc, c[3] * sc);
        }
    }
}

// ============================================================================
// Causal row softmax, in place.
// ============================================================================
__global__ __launch_bounds__(256) void softmax_kernel(float* __restrict__ attn)
{
    const int q = blockIdx.x, z = blockIdx.y;
    float* row = attn + ((size_t)z * S_ + q) * S_;
    const int L = q + 1, t = threadIdx.x;
    __shared__ float red[256];

    float m = -1e30f;
    for (int k = t; k < L; k += 256) m = fmaxf(m, row[k]);
    red[t] = m; __syncthreads();
    for (int s = 128; s > 0; s >>= 1) { if (t < s) red[t] = fmaxf(red[t], red[t + s]); __syncthreads(); }
    m = red[0]; __syncthreads();

    float sum = 0.0f;
    for (int k = t; k < L; k += 256) { float e = __expf(row[k] - m); row[k] = e; sum += e; }
    red[t] = sum; __syncthreads();
    for (int s = 128; s > 0; s >>= 1) { if (t < s) red[t] += red[t + s]; __syncthreads(); }
    const float inv = 1.0f / red[0];
    __syncthreads();

    for (int k = t; k < L; k += 256) row[k] *= inv;
    for (int k = L + t; k < S_; k += 256) row[k] = 0.0f;
}

// ============================================================================
// PV (plain tf32): ctx[b,q,h*64+d] = sum_k attn[z,q,k] * Vh[z,k,d].
// Block tile 128(q) x 64(d), K-chunk 32 over k in [0, q0+128).
// 8 warps = 4(m) x 2(n); warp tile 32x32 (mt=2, nt=4).
// ============================================================================
#define VSTR 68
__global__ __launch_bounds__(256) void pv_mma(
    const float* __restrict__ attn, const float* __restrict__ Vh,
    float* __restrict__ ctx)
{
    const int q0 = blockIdx.x * 128, z = blockIdx.y;
    const int bb = z >> 4, hh = z & 15;

    __shared__ float sA[128 * SSTR];   // attn tile [q][k], stride 36
    __shared__ float sV[32 * VSTR];    // V tile [k][d], stride 68

    const int t = threadIdx.x;
    const int wid = t >> 5, lane = t & 31, g = lane >> 2, tig = lane & 3;
    const int wm = wid & 3, wn = wid >> 2;

    const float* A = attn + (size_t)z * S_ * S_;
    const float* V = Vh + (size_t)z * S_ * DK_;

    float acc[2][4][4];
    #pragma unroll
    for (int mt = 0; mt < 2; mt++)
        #pragma unroll
        for (int nt = 0; nt < 4; nt++)
            #pragma unroll
            for (int i = 0; i < 4; i++) acc[mt][nt][i] = 0.0f;

    const int nch = (q0 + 128) >> 5;
    for (int kc = 0; kc < nch; ++kc) {
        const int k0 = kc * 32;
        __syncthreads();
        #pragma unroll
        for (int i = 0; i < 4; ++i) {   // attn tile 128x32
            int idx = i * 256 + t;
            int row = idx >> 3, c4 = (idx & 7) << 2;
            float4 av = *(const float4*)(A + (size_t)(q0 + row) * S_ + k0 + c4);
            *(float4*)(sA + row * SSTR + c4) =
                make_float4(tf32r(av.x), tf32r(av.y), tf32r(av.z), tf32r(av.w));
        }
        #pragma unroll
        for (int i = 0; i < 2; ++i) {   // V tile 32x64
            int idx = i * 256 + t;
            int row = idx >> 4, c4 = (idx & 15) << 2;
            float4 vv = *(const float4*)(V + (size_t)(k0 + row) * DK_ + c4);
            *(float4*)(sV + row * VSTR + c4) =
                make_float4(tf32r(vv.x), tf32r(vv.y), tf32r(vv.z), tf32r(vv.w));
        }
        __syncthreads();

        #pragma unroll
        for (int kk = 0; kk < 32; kk += 8) {
            uint32_t a[2][4];
            #pragma unroll
            for (int mt = 0; mt < 2; mt++) {
                int m = wm * 32 + mt * 16;
                a[mt][0] = fu(sA[(m + g)     * SSTR + kk + tig]);
                a[mt][1] = fu(sA[(m + g + 8) * SSTR + kk + tig]);
                a[mt][2] = fu(sA[(m + g)     * SSTR + kk + tig + 4]);
                a[mt][3] = fu(sA[(m + g + 8) * SSTR + kk + tig + 4]);
            }
            uint32_t b[4][2];
            #pragma unroll
            for (int nt = 0; nt < 4; nt++) {
                int n = wn * 32 + nt * 8;
                b[nt][0] = fu(sV[(kk + tig)     * VSTR + n + g]);
                b[nt][1] = fu(sV[(kk + tig + 4) * VSTR + n + g]);
            }
            #pragma unroll
            for (int mt = 0; mt < 2; mt++)
                #pragma unroll
                for (int nt = 0; nt < 4; nt++)
                    mma8(acc[mt][nt], a[mt][0], a[mt][1], a[mt][2], a[mt][3],
                         b[nt][0], b[nt][1]);
        }
    }

    #pragma unroll
    for (int mt = 0; mt < 2; mt++) {
        int q = q0 + wm * 32 + mt * 16 + g;
        float* d0p = ctx + ((size_t)bb * S_ + q) * D_ + hh * DK_;
        float* d1p = d0p + 8 * D_;
        #pragma unroll
        for (int nt = 0; nt < 4; nt++) {
            int col = wn * 32 + nt * 8 + 2 * tig;
            float* c = acc[mt][nt];
            *(float2*)(d0p + col) = make_float2(c[0], c[1]);
            *(float2*)(d1p + col) = make_float2(c[2], c[3]);
        }
    }
}

// ============================================================================
extern "C" void kernel_launch(void* const* d_in, const int* in_sizes, int n_in,
                              void* d_out, int out_size)
{
    const float* q  = (const float*)d_in[0];
    const float* k  = (const float*)d_in[1];
    const float* v  = (const float*)d_in[2];
    const float* Wq = (const float*)d_in[5];
    const float* bq = (const float*)d_in[6];
    const float* Wk = (const float*)d_in[7];
    const float* bk = (const float*)d_in[8];
    const float* Wv = (const float*)d_in[9];
    const float* bv = (const float*)d_in[10];
    const float* Wo = (const float*)d_in[11];
    const float* bo = (const float*)d_in[12];

    float *gQh, *gKh, *gVh, *gCtx, *gAttn, *gOutSpare;
    cudaGetSymbolAddress((void**)&gQh,  g_Qh);
    cudaGetSymbolAddress((void**)&gKh,  g_Kh);
    cudaGetSymbolAddress((void**)&gVh,  g_Vh);
    cudaGetSymbolAddress((void**)&gCtx, g_Ctx);
    cudaGetSymbolAddress((void**)&gAttn, g_Attn);
    cudaGetSymbolAddress((void**)&gOutSpare, g_OutSpare);

    float* outp = (float*)d_out;
    float* attn = gAttn;
    if ((size_t)out_size == BSD + BHSS) {
        outp = (float*)d_out;
        attn = (float*)d_out + BSD;
    } else if ((size_t)out_size == BHSS) {
        attn = (float*)d_out;
        outp = gOutSpare;
    }

    const dim3 blk(256);
    const dim3 gProj(D_ / 128, (B_ * S_) / 128);     // (8, 32)

    proj_mma<<<gProj, blk>>>(q, Wq, bq, gQh, 1);
    proj_mma<<<gProj, blk>>>(k, Wk, bk, gKh, 1);
    proj_mma<<<gProj, blk>>>(v, Wv, bv, gVh, 1);

    scores_mma<<<dim3(S_ / 128, S_ / 128, B_ * H_), blk>>>(gQh, gKh, attn);
    softmax_kernel<<<dim3(S_, B_ * H_), blk>>>(attn);
    pv_mma<<<dim3(S_ / 128, B_ * H_), blk>>>(attn, gVh, gCtx);

    proj_mma<<<gProj, blk>>>(gCtx, Wo, bo, outp, 0);
}

// round 5
// speedup vs baseline: 3.2313x; 1.9125x over previous
#include <cuda_runtime.h>
#include <cuda_fp16.h>
#include <cstdint>

#define B_ 2
#define S_ 2048
#define D_ 1024
#define H_ 16
#define DK_ 64

static const size_t BSD  = (size_t)B_ * S_ * D_;            // 4,194,304
static const size_t BHSS = (size_t)B_ * H_ * S_ * S_;       // 134,217,728

// Device scratch (allocation-free rule)
__device__ __align__(256) __half g_Qh[B_ * H_ * S_ * DK_];  // [z,s,dk] fp16
__device__ __align__(256) __half g_Kh[B_ * H_ * S_ * DK_];  // [z,s,dk] fp16
__device__ __align__(256) __half g_Vt[B_ * H_ * DK_ * S_];  // [z,dk,s] fp16 (transposed)
__device__ __align__(256) float  g_Ctx[B_ * S_ * D_];       // [b,s,D]
__device__ __align__(256) float  g_Attn[(size_t)B_ * H_ * S_ * S_]; // scratch if attn not output
__device__ __align__(256) float  g_OutSpare[B_ * S_ * D_];

// ------------------------- helpers -------------------------
__device__ __forceinline__ void mma16(float* c,
    uint32_t a0, uint32_t a1, uint32_t a2, uint32_t a3,
    uint32_t b0, uint32_t b1)
{
    asm volatile(
        "mma.sync.aligned.m16n8k16.row.col.f32.f16.f16.f32 "
        "{%0,%1,%2,%3}, {%4,%5,%6,%7}, {%8,%9}, {%0,%1,%2,%3};"
        : "+f"(c[0]), "+f"(c[1]), "+f"(c[2]), "+f"(c[3])
        : "r"(a0), "r"(a1), "r"(a2), "r"(a3), "r"(b0), "r"(b1));
}
__device__ __forceinline__ uint32_t h2u(__half2 h) { return *(uint32_t*)&h; }

// ============================================================================
// Projection (fp16x2 split): Y = X @ W^T + bias.
// X:[4096,1024] f32, W:[1024,1024] f32. BM=128, BN=128, BK=32.
// 8 warps = 4(m) x 2(n); warp tile 32x64 (mt=2, nt=8).
// mode 0: Y f32 [m,1024]; mode 1: Y fp16 head-major [z,s,64];
// mode 2: Y fp16 transposed-V [z,dk,s].
// ============================================================================
#define PSTRH 40   // halves per row (32 + 8 pad); row stride 80B
__global__ __launch_bounds__(256) void proj_h(
    const float* __restrict__ X, const float* __restrict__ W,
    const float* __restrict__ bias, void* __restrict__ Yv, int mode)
{
    __shared__ __half sXh[128 * PSTRH], sXl[128 * PSTRH];
    __shared__ __half sWh[128 * PSTRH], sWl[128 * PSTRH];

    const int t = threadIdx.x;
    const int wid = t >> 5, lane = t & 31, g = lane >> 2, tig = lane & 3;
    const int wm = wid & 3, wn = wid >> 2;
    const int bn = blockIdx.x * 128, bm = blockIdx.y * 128;

    float acc[2][8][4];
    #pragma unroll
    for (int mt = 0; mt < 2; mt++)
        #pragma unroll
        for (int nt = 0; nt < 8; nt++)
            #pragma unroll
            for (int i = 0; i < 4; i++) acc[mt][nt][i] = 0.0f;

    for (int k0 = 0; k0 < D_; k0 += 32) {
        __syncthreads();
        #pragma unroll
        for (int i = 0; i < 8; ++i) {          // 128 rows x 16 half2-cols
            int idx = i * 256 + t;
            int row = idx >> 4, kp = idx & 15;  // cols 2kp, 2kp+1
            int so = row * PSTRH + 2 * kp;
            float2 xv = *(const float2*)(X + (size_t)(bm + row) * D_ + k0 + 2 * kp);
            __half hx0 = __float2half_rn(xv.x), hx1 = __float2half_rn(xv.y);
            __half lx0 = __float2half_rn(xv.x - __half2float(hx0));
            __half lx1 = __float2half_rn(xv.y - __half2float(hx1));
            *(__half2*)(sXh + so) = __halves2half2(hx0, hx1);
            *(__half2*)(sXl + so) = __halves2half2(lx0, lx1);
            float2 wv = *(const float2*)(W + (size_t)(bn + row) * D_ + k0 + 2 * kp);
            __half hw0 = __float2half_rn(wv.x), hw1 = __float2half_rn(wv.y);
            __half lw0 = __float2half_rn(wv.x - __half2float(hw0));
            __half lw1 = __float2half_rn(wv.y - __half2float(hw1));
            *(__half2*)(sWh + so) = __halves2half2(hw0, hw1);
            *(__half2*)(sWl + so) = __halves2half2(lw0, lw1);
        }
        __syncthreads();

        #pragma unroll
        for (int kk = 0; kk < 32; kk += 16) {
            uint32_t ah[2][4], al[2][4];
            #pragma unroll
            for (int mt = 0; mt < 2; mt++) {
                int m = wm * 32 + mt * 16;
                int base = (m + g) * PSTRH + kk + 2 * tig;
                ah[mt][0] = *(const uint32_t*)(sXh + base);
                ah[mt][1] = *(const uint32_t*)(sXh + base + 8 * PSTRH);
                ah[mt][2] = *(const uint32_t*)(sXh + base + 8);
                ah[mt][3] = *(const uint32_t*)(sXh + base + 8 * PSTRH + 8);
                al[mt][0] = *(const uint32_t*)(sXl + base);
                al[mt][1] = *(const uint32_t*)(sXl + base + 8 * PSTRH);
                al[mt][2] = *(const uint32_t*)(sXl + base + 8);
                al[mt][3] = *(const uint32_t*)(sXl + base + 8 * PSTRH + 8);
            }
            #pragma unroll
            for (int nt = 0; nt < 8; nt++) {
                int n = wn * 64 + nt * 8;
                int base = (n + g) * PSTRH + kk + 2 * tig;
                uint32_t bh0 = *(const uint32_t*)(sWh + base);
                uint32_t bh1 = *(const uint32_t*)(sWh + base + 8);
                uint32_t bl0 = *(const uint32_t*)(sWl + base);
                uint32_t bl1 = *(const uint32_t*)(sWl + base + 8);
                #pragma unroll
                for (int mt = 0; mt < 2; mt++) {
                    mma16(acc[mt][nt], ah[mt][0], ah[mt][1], ah[mt][2], ah[mt][3], bh0, bh1);
                    mma16(acc[mt][nt], ah[mt][0], ah[mt][1], ah[mt][2], ah[mt][3], bl0, bl1);
                    mma16(acc[mt][nt], al[mt][0], al[mt][1], al[mt][2], al[mt][3], bh0, bh1);
                }
            }
        }
    }

    // epilogue
    #pragma unroll
    for (int mt = 0; mt < 2; mt++) {
        int r0 = bm + wm * 32 + mt * 16 + g;
        int r1 = r0 + 8;
        #pragma unroll
        for (int nt = 0; nt < 8; nt++) {
            int col = bn + wn * 64 + nt * 8 + 2 * tig;
            float b0v = __ldg(bias + col), b1v = __ldg(bias + col + 1);
            float* c = acc[mt][nt];
            float v00 = c[0] + b0v, v01 = c[1] + b1v;
            float v10 = c[2] + b0v, v11 = c[3] + b1v;
            if (mode == 0) {
                float* Y = (float*)Yv;
                *(float2*)(Y + (size_t)r0 * D_ + col) = make_float2(v00, v01);
                *(float2*)(Y + (size_t)r1 * D_ + col) = make_float2(v10, v11);
            } else if (mode == 1) {
                __half* Y = (__half*)Yv;
                int h = col >> 6, d0 = col & 63;
                int bb0 = r0 >> 11, ss0 = r0 & (S_ - 1);
                int bb1 = r1 >> 11, ss1 = r1 & (S_ - 1);
                *(__half2*)(Y + (((size_t)bb0 * H_ + h) * S_ + ss0) * DK_ + d0) =
                    __floats2half2_rn(v00, v01);
                *(__half2*)(Y + (((size_t)bb1 * H_ + h) * S_ + ss1) * DK_ + d0) =
                    __floats2half2_rn(v10, v11);
            } else {   // transposed V: Vt[(z*64 + d) * S + s]
                __half* Y = (__half*)Yv;
                int h = col >> 6, d0 = col & 63;
                int bb0 = r0 >> 11, ss0 = r0 & (S_ - 1);
                int bb1 = r1 >> 11, ss1 = r1 & (S_ - 1);
                size_t z0 = (size_t)bb0 * H_ + h, z1 = (size_t)bb1 * H_ + h;
                Y[(z0 * DK_ + d0)     * S_ + ss0] = __float2half_rn(v00);
                Y[(z0 * DK_ + d0 + 1) * S_ + ss0] = __float2half_rn(v01);
                Y[(z1 * DK_ + d0)     * S_ + ss1] = __float2half_rn(v10);
                Y[(z1 * DK_ + d0 + 1) * S_ + ss1] = __float2half_rn(v11);
            }
        }
    }
}

// ============================================================================
// Fused flash attention (two-pass) + attn materialization.
// Block: 128 q-rows x one z. 8 warps, warp w owns q-rows [q0+16w, +16).
// Key tiles of 64. Pass A: online row max/sum. Pass B: recompute scores,
// p = exp(s-m)/l  -> write attn, convert in-register to A-fragments -> PV mma.
// ============================================================================
#define FSTR 72   // halves per smem row (64 + 8 pad); 144B, 16B-aligned
__global__ __launch_bounds__(256) void attn_fused(
    const __half* __restrict__ Qh, const __half* __restrict__ Kh,
    const __half* __restrict__ Vt, float* __restrict__ attn,
    float* __restrict__ ctx, int write_attn)
{
    const int qb = (int)gridDim.x - 1 - blockIdx.x;   // long blocks first
    const int q0 = qb * 128;
    const int z = blockIdx.y, bb = z >> 4, hh = z & 15;

    __shared__ __half sK[64 * FSTR];
    __shared__ __half sV[64 * FSTR];

    const int t = threadIdx.x, wid = t >> 5, lane = t & 31;
    const int g = lane >> 2, tig = lane & 3;
    const __half* Q = Qh + (size_t)z * S_ * DK_;
    const __half* K = Kh + (size_t)z * S_ * DK_;
    const __half* V = Vt + (size_t)z * DK_ * S_;
    float* A = attn + (size_t)z * S_ * S_;

    const int r0 = q0 + wid * 16 + g, r1 = r0 + 8;

    // Q fragments for dk=64: 4 k-steps x 4 regs, held in registers
    uint32_t qa[4][4];
    #pragma unroll
    for (int kk = 0; kk < 4; kk++) {
        qa[kk][0] = *(const uint32_t*)(Q + (size_t)r0 * DK_ + kk * 16 + 2 * tig);
        qa[kk][1] = *(const uint32_t*)(Q + (size_t)r1 * DK_ + kk * 16 + 2 * tig);
        qa[kk][2] = *(const uint32_t*)(Q + (size_t)r0 * DK_ + kk * 16 + 2 * tig + 8);
        qa[kk][3] = *(const uint32_t*)(Q + (size_t)r1 * DK_ + kk * 16 + 2 * tig + 8);
    }

    float m0 = -1e30f, m1 = -1e30f, l0 = 0.0f, l1 = 0.0f;
    const int ntl = (q0 + 128) / 64;
    const float sc = 0.125f;

    // ---------------- Pass A: online max / sum ----------------
    for (int kt = 0; kt < ntl; kt++) {
        const int k0 = kt * 64;
        __syncthreads();
        #pragma unroll
        for (int i = 0; i < 2; i++) {
            int idx = i * 256 + t, row = idx >> 3, c = idx & 7;
            *(uint4*)(sK + row * FSTR + c * 8) =
                *(const uint4*)(K + (size_t)(k0 + row) * DK_ + c * 8);
        }
        __syncthreads();

        float sacc[8][4];
        #pragma unroll
        for (int nt = 0; nt < 8; nt++)
            #pragma unroll
            for (int e = 0; e < 4; e++) sacc[nt][e] = 0.0f;
        #pragma unroll
        for (int kk = 0; kk < 4; kk++)
            #pragma unroll
            for (int nt = 0; nt < 8; nt++) {
                int base = (nt * 8 + g) * FSTR + kk * 16 + 2 * tig;
                uint32_t b0 = *(const uint32_t*)(sK + base);
                uint32_t b1 = *(const uint32_t*)(sK + base + 8);
                mma16(sacc[nt], qa[kk][0], qa[kk][1], qa[kk][2], qa[kk][3], b0, b1);
            }

        const bool edge = (k0 + 63 > q0 + wid * 16);
        float tm0 = -1e30f, tm1 = -1e30f;
        #pragma unroll
        for (int nt = 0; nt < 8; nt++) {
            int kc = k0 + nt * 8 + 2 * tig;
            float s0 = sacc[nt][0] * sc, s1 = sacc[nt][1] * sc;
            float s2 = sacc[nt][2] * sc, s3 = sacc[nt][3] * sc;
            if (edge) {
                if (kc     > r0) s0 = -1e30f;
                if (kc + 1 > r0) s1 = -1e30f;
                if (kc     > r1) s2 = -1e30f;
                if (kc + 1 > r1) s3 = -1e30f;
            }
            sacc[nt][0] = s0; sacc[nt][1] = s1; sacc[nt][2] = s2; sacc[nt][3] = s3;
            tm0 = fmaxf(tm0, fmaxf(s0, s1));
            tm1 = fmaxf(tm1, fmaxf(s2, s3));
        }
        tm0 = fmaxf(tm0, __shfl_xor_sync(0xffffffffu, tm0, 1));
        tm0 = fmaxf(tm0, __shfl_xor_sync(0xffffffffu, tm0, 2));
        tm1 = fmaxf(tm1, __shfl_xor_sync(0xffffffffu, tm1, 1));
        tm1 = fmaxf(tm1, __shfl_xor_sync(0xffffffffu, tm1, 2));
        float mn0 = fmaxf(m0, tm0), mn1 = fmaxf(m1, tm1);

        float su0 = 0.0f, su1 = 0.0f;
        #pragma unroll
        for (int nt = 0; nt < 8; nt++) {
            su0 += __expf(sacc[nt][0] - mn0) + __expf(sacc[nt][1] - mn0);
            su1 += __expf(sacc[nt][2] - mn1) + __expf(sacc[nt][3] - mn1);
        }
        su0 += __shfl_xor_sync(0xffffffffu, su0, 1);
        su0 += __shfl_xor_sync(0xffffffffu, su0, 2);
        su1 += __shfl_xor_sync(0xffffffffu, su1, 1);
        su1 += __shfl_xor_sync(0xffffffffu, su1, 2);

        l0 = l0 * __expf(m0 - mn0) + su0; m0 = mn0;
        l1 = l1 * __expf(m1 - mn1) + su1; m1 = mn1;
    }
    const float inv0 = 1.0f / l0, inv1 = 1.0f / l1;

    // ---------------- Pass B: recompute, write p, PV ----------------
    float pv[8][4];
    #pragma unroll
    for (int dt = 0; dt < 8; dt++)
        #pragma unroll
        for (int e = 0; e < 4; e++) pv[dt][e] = 0.0f;

    for (int kt = 0; kt < ntl; kt++) {
        const int k0 = kt * 64;
        __syncthreads();
        #pragma unroll
        for (int i = 0; i < 2; i++) {
            int idx = i * 256 + t, row = idx >> 3, c = idx & 7;
            *(uint4*)(sK + row * FSTR + c * 8) =
                *(const uint4*)(K + (size_t)(k0 + row) * DK_ + c * 8);
            *(uint4*)(sV + row * FSTR + c * 8) =
                *(const uint4*)(V + (size_t)row * S_ + k0 + c * 8);
        }
        __syncthreads();

        float sacc[8][4];
        #pragma unroll
        for (int nt = 0; nt < 8; nt++)
            #pragma unroll
            for (int e = 0; e < 4; e++) sacc[nt][e] = 0.0f;
        #pragma unroll
        for (int kk = 0; kk < 4; kk++)
            #pragma unroll
            for (int nt = 0; nt < 8; nt++) {
                int base = (nt * 8 + g) * FSTR + kk * 16 + 2 * tig;
                uint32_t b0 = *(const uint32_t*)(sK + base);
                uint32_t b1 = *(const uint32_t*)(sK + base + 8);
                mma16(sacc[nt], qa[kk][0], qa[kk][1], qa[kk][2], qa[kk][3], b0, b1);
            }

        const bool edge = (k0 + 63 > q0 + wid * 16);
        uint32_t pa[4][4];
        #pragma unroll
        for (int nt = 0; nt < 8; nt++) {
            int kc = k0 + nt * 8 + 2 * tig;
            float s0 = sacc[nt][0] * sc, s1 = sacc[nt][1] * sc;
            float s2 = sacc[nt][2] * sc, s3 = sacc[nt][3] * sc;
            if (edge) {
                if (kc     > r0) s0 = -1e30f;
                if (kc + 1 > r0) s1 = -1e30f;
                if (kc     > r1) s2 = -1e30f;
                if (kc + 1 > r1) s3 = -1e30f;
            }
            float p0 = __expf(s0 - m0) * inv0;
            float p1 = __expf(s1 - m0) * inv0;
            float p2 = __expf(s2 - m1) * inv1;
            float p3 = __expf(s3 - m1) * inv1;
            if (write_attn) {
                *(float2*)(A + (size_t)r0 * S_ + kc) = make_float2(p0, p1);
                *(float2*)(A + (size_t)r1 * S_ + kc) = make_float2(p2, p3);
            }
            // accumulator layout -> A-fragment layout, in-register
            uint32_t h01 = h2u(__floats2half2_rn(p0, p1));
            uint32_t h23 = h2u(__floats2half2_rn(p2, p3));
            int ks = nt >> 1;
            if ((nt & 1) == 0) { pa[ks][0] = h01; pa[ks][1] = h23; }
            else               { pa[ks][2] = h01; pa[ks][3] = h23; }
        }
        #pragma unroll
        for (int kk = 0; kk < 4; kk++)
            #pragma unroll
            for (int dt = 0; dt < 8; dt++) {
                int base = (dt * 8 + g) * FSTR + kk * 16 + 2 * tig;
                uint32_t b0 = *(const uint32_t*)(sV + base);
                uint32_t b1 = *(const uint32_t*)(sV + base + 8);
                mma16(pv[dt], pa[kk][0], pa[kk][1], pa[kk][2], pa[kk][3], b0, b1);
            }
    }

    // ctx epilogue
    #pragma unroll
    for (int dt = 0; dt < 8; dt++) {
        int col = dt * 8 + 2 * tig;
        *(float2*)(ctx + ((size_t)bb * S_ + r0) * D_ + hh * DK_ + col) =
            make_float2(pv[dt][0], pv[dt][1]);
        *(float2*)(ctx + ((size_t)bb * S_ + r1) * D_ + hh * DK_ + col) =
            make_float2(pv[dt][2], pv[dt][3]);
    }

    // causal zero tail: cols [q0+128, S)
    if (write_attn) {
        const int kend = q0 + 128;
        if (kend < S_) {
            for (int rr = 0; rr < 16; rr++) {
                int row = q0 + wid * 16 + rr;
                float* rp = A + (size_t)row * S_;
                for (int c = kend + lane * 4; c < S_; c += 128)
                    *(float4*)(rp + c) = make_float4(0.f, 0.f, 0.f, 0.f);
            }
        }
    }
}

// ============================================================================
extern "C" void kernel_launch(void* const* d_in, const int* in_sizes, int n_in,
                              void* d_out, int out_size)
{
    const float* q  = (const float*)d_in[0];
    const float* k  = (const float*)d_in[1];
    const float* v  = (const float*)d_in[2];
    const float* Wq = (const float*)d_in[5];
    const float* bq = (const float*)d_in[6];
    const float* Wk = (const float*)d_in[7];
    const float* bk = (const float*)d_in[8];
    const float* Wv = (const float*)d_in[9];
    const float* bv = (const float*)d_in[10];
    const float* Wo = (const float*)d_in[11];
    const float* bo = (const float*)d_in[12];

    __half *gQh, *gKh, *gVt;
    float *gCtx, *gAttn, *gOutSpare;
    cudaGetSymbolAddress((void**)&gQh,  g_Qh);
    cudaGetSymbolAddress((void**)&gKh,  g_Kh);
    cudaGetSymbolAddress((void**)&gVt,  g_Vt);
    cudaGetSymbolAddress((void**)&gCtx, g_Ctx);
    cudaGetSymbolAddress((void**)&gAttn, g_Attn);
    cudaGetSymbolAddress((void**)&gOutSpare, g_OutSpare);

    float* outp = (float*)d_out;
    float* attn = gAttn;
    int write_attn = 0;
    if ((size_t)out_size == BSD + BHSS) {
        outp = (float*)d_out;
        attn = (float*)d_out + BSD;
        write_attn = 1;
    } else if ((size_t)out_size == BHSS) {
        attn = (float*)d_out;
        outp = gOutSpare;
        write_attn = 1;
    }

    const dim3 blk(256);
    const dim3 gProj(D_ / 128, (B_ * S_) / 128);     // (8, 32)

    proj_h<<<gProj, blk>>>(q, Wq, bq, (void*)gQh, 1);
    proj_h<<<gProj, blk>>>(k, Wk, bk, (void*)gKh, 1);
    proj_h<<<gProj, blk>>>(v, Wv, bv, (void*)gVt, 2);

    attn_fused<<<dim3(S_ / 128, B_ * H_), blk>>>(gQh, gKh, gVt, attn, gCtx, write_attn);

    proj_h<<<gProj, blk>>>(gCtx, Wo, bo, (void*)outp, 0);
}